// round 16
// baseline (speedup 1.0000x reference)
#include <cuda_runtime.h>
#include <cuda_bf16.h>
#include <cuda_fp16.h>
#include <cstdint>

#define Hd 1024
#define Bd 64
#define Sd 512
#define NCd 20
#define NNd 15
#define OPd 5
#define NTOT 35
#define NEGV (-1e12f)

// ---------------- scratch (device globals; no allocation allowed) ----------------
__device__ float g_node[Bd * Hd];
__device__ float g_cnode[Bd * Hd];
__device__ float g_energy[Bd * Sd];
__device__ float g_cat[Bd * 2 * Hd];
__device__ float g_leaf[Bd * Hd];
__device__ float g_cnum[Bd * Hd];
__device__ float g_cop[Bd * Hd];
__device__ float g_spre[Bd * NTOT + Bd * OPd];
__device__ __half g_ench[32768 * 1024];          // enc fp16 (64 MB)
__device__ __half g_wah[1024 * 1024];            // Wa[:, Hd:2Hd] fp16
__device__ __half g_wnah[1024 * 2048];           // Wna[:, Hd:3Hd] fp16
__device__ __half g_woah[1024 * 2048];           // Woa[:, Hd:3Hd] fp16
__device__ __half g_aexth[2560 * 2048];          // [emb | leaf*emb] fp16 rows

// ================= helpers =================
__device__ __forceinline__ uint32_t smem_u32(const void* p) {
    uint32_t a;
    asm("{ .reg .u64 t; cvta.to.shared.u64 t, %1; cvt.u32.u64 %0, t; }" : "=r"(a) : "l"(p));
    return a;
}
__device__ __forceinline__ void cpasync16(uint32_t saddr, const void* g) {
    asm volatile("cp.async.cg.shared.global [%0], [%1], 16;" :: "r"(saddr), "l"(g));
}
#define CP_COMMIT() asm volatile("cp.async.commit_group;" ::: "memory")
#define CP_WAIT2()  asm volatile("cp.async.wait_group 2;" ::: "memory")
#define CP_WAIT1()  asm volatile("cp.async.wait_group 1;" ::: "memory")
#define CP_WAIT0()  asm volatile("cp.async.wait_group 0;" ::: "memory")

// ---------------- fp32 -> fp16 convert pre-passes ----------------
__device__ __forceinline__ void cvt_store4(__half* dst, float4 a) {
    __half2 h0 = __floats2half2_rn(a.x, a.y);
    __half2 h1 = __floats2half2_rn(a.z, a.w);
    uint2 u;
    u.x = *(uint32_t*)&h0; u.y = *(uint32_t*)&h1;
    *(uint2*)dst = u;
}
__global__ void cvt_enc_kernel(const float* __restrict__ enc, const float* __restrict__ Wa) {
    const int EN4 = (32768 * 1024) / 4;
    int i = blockIdx.x * blockDim.x + threadIdx.x;
    if (i < EN4) {
        cvt_store4(g_ench + (size_t)i * 4, ((const float4*)enc)[i]);
        return;
    }
    i -= EN4;
    if (i < (1024 * 1024) / 4) {
        int n = i >> 8, c = i & 255;
        cvt_store4(g_wah + (size_t)n * 1024 + c * 4,
                   *(const float4*)(Wa + (size_t)n * 2048 + 1024 + c * 4));
    }
}
__global__ void cvt_w_kernel(const float* __restrict__ Wna, const float* __restrict__ Woa) {
    const int WX4 = (1024 * 2048) / 4;
    int i = blockIdx.x * blockDim.x + threadIdx.x;
    if (i < WX4) {
        int n = i >> 9, c = i & 511;
        cvt_store4(g_wnah + (size_t)n * 2048 + c * 4,
                   *(const float4*)(Wna + (size_t)n * 3072 + 1024 + c * 4));
        return;
    }
    i -= WX4;
    if (i < WX4) {
        int n = i >> 9, c = i & 511;
        cvt_store4(g_woah + (size_t)n * 2048 + c * 4,
                   *(const float4*)(Woa + (size_t)n * 3072 + 1024 + c * 4));
    }
}

// ---------------- fp16 A-rows for score heads, split halves ----------------
__global__ void prep_emb(const float* __restrict__ ocn, const float* __restrict__ opemb) {
    int i = blockIdx.x * blockDim.x + threadIdx.x;
    if (i >= 2560 * 1024) return;
    int r = i >> 10, h = i & (Hd - 1);
    float e;
    if (r < Bd * NTOT) e = ocn[(size_t)r * Hd + h];
    else {
        int rr = r - Bd * NTOT;
        e = opemb[(size_t)(rr % OPd) * Hd + h];
    }
    g_aexth[(size_t)r * 2048 + h] = __float2half(e);
}
__global__ void prep_leafemb(const float* __restrict__ ocn, const float* __restrict__ opemb) {
    int i = blockIdx.x * blockDim.x + threadIdx.x;
    if (i >= 2560 * 1024) return;
    int r = i >> 10, h = i & (Hd - 1);
    float e;
    int b;
    if (r < Bd * NTOT) { b = r / NTOT; e = ocn[(size_t)r * Hd + h]; }
    else {
        int rr = r - Bd * NTOT;
        b = rr / OPd;
        e = opemb[(size_t)(rr % OPd) * Hd + h];
    }
    g_aexth[(size_t)r * 2048 + Hd + h] = __float2half(e * g_leaf[(size_t)b * Hd + h]);
}

#define FP2 20

// =================================================================================
// Energies GEMM: 256 threads, 8 warps (4x2), warp tile 32x64, CTA 128x128,
// 4-stage cp.async, ldmatrix, 2 CTA/SM.
// =================================================================================
#define ESTG ((128 + 128) * FP2)
#define ESMEM (4 * ESTG * 4)

__global__ __launch_bounds__(256, 2) void mma_energy256(
    const __half* __restrict__ Ah, const __half* __restrict__ Bh,
    const float* __restrict__ Cb, const float* __restrict__ v,
    float* __restrict__ outp)
{
    extern __shared__ __align__(16) uint32_t fsm[];
    const int tid = threadIdx.x;
    const int n0 = blockIdx.x * 128;
    const int m0 = blockIdx.y * 128;
    const int warp = tid >> 5, lane = tid & 31;
    const int g = lane >> 2, tig = lane & 3;
    const int wm = (warp & 3) * 32;
    const int wn = (warp >> 2) * 64;
    const uint32_t sbase = smem_u32(fsm);

    const int aro = (lane & 7) | (lane & 8);
    const int aco = (lane & 16) ? 4 : 0;
    const int bro = (lane & 7) | ((lane & 16) >> 1);
    const int bco = (lane & 8) >> 1;

    float acc[2][8][4];
#pragma unroll
    for (int mt = 0; mt < 2; mt++)
#pragma unroll
        for (int nt = 0; nt < 8; nt++)
#pragma unroll
            for (int c = 0; c < 4; c++) acc[mt][nt][c] = 0.f;

#define EPF(c_) do {                                                              \
    const uint32_t _sb = sbase + (uint32_t)((c_) & 3) * (ESTG * 4);               \
    const int _k0 = (c_) * 32;                                                    \
    _Pragma("unroll")                                                             \
    for (int it = 0; it < 2; it++) {                                              \
        int idx = tid + it * 256; int r = idx >> 2, pp = idx & 3;                 \
        cpasync16(_sb + (uint32_t)(r * FP2 + pp * 4) * 4,                         \
                  Ah + (size_t)(m0 + r) * 1024 + _k0 + pp * 8);                   \
    }                                                                             \
    _Pragma("unroll")                                                             \
    for (int it = 0; it < 2; it++) {                                              \
        int idx = tid + it * 256; int r = idx >> 2, pp = idx & 3;                 \
        cpasync16(_sb + (uint32_t)((128 * FP2 + r * FP2 + pp * 4)) * 4,           \
                  Bh + (size_t)(n0 + r) * 1024 + _k0 + pp * 8);                   \
    }                                                                             \
    CP_COMMIT();                                                                  \
} while (0)

    EPF(0); EPF(1); EPF(2);

    for (int c = 0; c < 32; c++) {
        const int rem = 31 - c;
        if (rem >= 2) CP_WAIT2(); else if (rem == 1) CP_WAIT1(); else CP_WAIT0();
        __syncthreads();
        if (c + 3 < 32) EPF(c + 3);

        const uint32_t stg = sbase + (uint32_t)(c & 3) * (ESTG * 4);

#pragma unroll
        for (int kk = 0; kk < 2; kk++) {
            uint32_t af[2][4];
#pragma unroll
            for (int mt = 0; mt < 2; mt++) {
                uint32_t aaddr = stg +
                    (uint32_t)(((wm + mt * 16 + aro) * FP2 + kk * 8 + aco) * 4);
                asm volatile(
                    "ldmatrix.sync.aligned.m8n8.x4.shared.b16 {%0,%1,%2,%3}, [%4];"
                    : "=r"(af[mt][0]), "=r"(af[mt][1]), "=r"(af[mt][2]), "=r"(af[mt][3])
                    : "r"(aaddr));
            }
            uint32_t bf[8][2];
#pragma unroll
            for (int p = 0; p < 4; p++) {
                uint32_t baddr = stg +
                    (uint32_t)((128 * FP2 + (wn + p * 16 + bro) * FP2 + kk * 8 + bco) * 4);
                asm volatile(
                    "ldmatrix.sync.aligned.m8n8.x4.shared.b16 {%0,%1,%2,%3}, [%4];"
                    : "=r"(bf[2 * p][0]), "=r"(bf[2 * p][1]),
                      "=r"(bf[2 * p + 1][0]), "=r"(bf[2 * p + 1][1])
                    : "r"(baddr));
            }
#pragma unroll
            for (int mt = 0; mt < 2; mt++)
#pragma unroll
                for (int nt = 0; nt < 8; nt++) {
                    asm volatile(
                        "mma.sync.aligned.m16n8k16.row.col.f32.f16.f16.f32 "
                        "{%0,%1,%2,%3}, {%4,%5,%6,%7}, {%8,%9}, {%0,%1,%2,%3};"
                        : "+f"(acc[mt][nt][0]), "+f"(acc[mt][nt][1]),
                          "+f"(acc[mt][nt][2]), "+f"(acc[mt][nt][3])
                        : "r"(af[mt][0]), "r"(af[mt][1]), "r"(af[mt][2]), "r"(af[mt][3]),
                          "r"(bf[nt][0]), "r"(bf[nt][1]));
                }
        }
    }

#pragma unroll
    for (int mt = 0; mt < 2; mt++) {
        const int r0 = m0 + wm + mt * 16 + g;
        const int r1 = r0 + 8;
        const int bi0 = r0 >> 9;
        const int bi1 = r1 >> 9;
        float p0 = 0.f, p1 = 0.f;
#pragma unroll
        for (int nt = 0; nt < 8; nt++) {
            const int n = n0 + wn + nt * 8 + tig * 2;
            const float v0 = v[n], v1 = v[n + 1];
            p0 = fmaf(v0, tanhf(acc[mt][nt][0] + Cb[(size_t)bi0 * Hd + n]), p0);
            p0 = fmaf(v1, tanhf(acc[mt][nt][1] + Cb[(size_t)bi0 * Hd + n + 1]), p0);
            p1 = fmaf(v0, tanhf(acc[mt][nt][2] + Cb[(size_t)bi1 * Hd + n]), p1);
            p1 = fmaf(v1, tanhf(acc[mt][nt][3] + Cb[(size_t)bi1 * Hd + n + 1]), p1);
        }
        p0 += __shfl_xor_sync(0xffffffffu, p0, 1);
        p0 += __shfl_xor_sync(0xffffffffu, p0, 2);
        p1 += __shfl_xor_sync(0xffffffffu, p1, 1);
        p1 += __shfl_xor_sync(0xffffffffu, p1, 2);
        if (tig == 0) {
            atomicAdd(&outp[r0], p0);
            atomicAdd(&outp[r1], p1);
        }
    }
}

// =================================================================================
// Score-head GEMM: 128 threads, CTA 64x128, warp tile 32x64
// =================================================================================
#define SSTG ((64 + 128) * FP2)
#define SSMEM (4 * SSTG * 4)

__global__ __launch_bounds__(128) void mma_f16_score(
    const __half* __restrict__ Ah, const __half* __restrict__ Bh,
    const float* __restrict__ Cb, const float* __restrict__ v,
    float* __restrict__ outp, int R, int rows_per_b, int K)
{
    extern __shared__ __align__(16) uint32_t fsm[];
    const int tid = threadIdx.x;
    const int n0 = blockIdx.x * 128;
    const int m0 = blockIdx.y * 64;
    const int warp = tid >> 5, lane = tid & 31;
    const int g = lane >> 2, tig = lane & 3;
    const int wm = (warp & 1) * 32;
    const int wn = (warp >> 1) * 64;
    const uint32_t sbase = smem_u32(fsm);
    const int nch = K >> 5;

    const int aro = (lane & 7) | (lane & 8);
    const int aco = (lane & 16) ? 4 : 0;
    const int bro = (lane & 7) | ((lane & 16) >> 1);
    const int bco = (lane & 8) >> 1;

    float acc[2][8][4];
#pragma unroll
    for (int mt = 0; mt < 2; mt++)
#pragma unroll
        for (int nt = 0; nt < 8; nt++)
#pragma unroll
            for (int c = 0; c < 4; c++) acc[mt][nt][c] = 0.f;

    auto prefetch = [&](int c_) {
        const uint32_t _sb = sbase + (uint32_t)(c_ & 3) * (SSTG * 4);
        const int _k0 = c_ * 32;
#pragma unroll
        for (int it = 0; it < 2; it++) {
            int idx = tid + it * 128; int r = idx >> 2, pp = idx & 3;
            int gr = m0 + r; if (gr >= R) gr = R - 1;
            cpasync16(_sb + (uint32_t)(r * FP2 + pp * 4) * 4,
                      Ah + (size_t)gr * K + _k0 + pp * 8);
        }
#pragma unroll
        for (int it = 0; it < 4; it++) {
            int idx = tid + it * 128; int r = idx >> 2, pp = idx & 3;
            cpasync16(_sb + (uint32_t)((64 * FP2 + r * FP2 + pp * 4)) * 4,
                      Bh + (size_t)(n0 + r) * K + _k0 + pp * 8);
        }
        CP_COMMIT();
    };

    prefetch(0); prefetch(1); prefetch(2);

    for (int c = 0; c < nch; c++) {
        const int rem = nch - 1 - c;
        if (rem >= 2) CP_WAIT2(); else if (rem == 1) CP_WAIT1(); else CP_WAIT0();
        __syncthreads();
        if (c + 3 < nch) prefetch(c + 3);

        const uint32_t stg = sbase + (uint32_t)(c & 3) * (SSTG * 4);

#pragma unroll
        for (int kk = 0; kk < 2; kk++) {
            uint32_t af[2][4];
#pragma unroll
            for (int mt = 0; mt < 2; mt++) {
                uint32_t aaddr = stg +
                    (uint32_t)(((wm + mt * 16 + aro) * FP2 + kk * 8 + aco) * 4);
                asm volatile(
                    "ldmatrix.sync.aligned.m8n8.x4.shared.b16 {%0,%1,%2,%3}, [%4];"
                    : "=r"(af[mt][0]), "=r"(af[mt][1]), "=r"(af[mt][2]), "=r"(af[mt][3])
                    : "r"(aaddr));
            }
            uint32_t bf[8][2];
#pragma unroll
            for (int p = 0; p < 4; p++) {
                uint32_t baddr = stg +
                    (uint32_t)((64 * FP2 + (wn + p * 16 + bro) * FP2 + kk * 8 + bco) * 4);
                asm volatile(
                    "ldmatrix.sync.aligned.m8n8.x4.shared.b16 {%0,%1,%2,%3}, [%4];"
                    : "=r"(bf[2 * p][0]), "=r"(bf[2 * p][1]),
                      "=r"(bf[2 * p + 1][0]), "=r"(bf[2 * p + 1][1])
                    : "r"(baddr));
            }
#pragma unroll
            for (int mt = 0; mt < 2; mt++)
#pragma unroll
                for (int nt = 0; nt < 8; nt++) {
                    asm volatile(
                        "mma.sync.aligned.m16n8k16.row.col.f32.f16.f16.f32 "
                        "{%0,%1,%2,%3}, {%4,%5,%6,%7}, {%8,%9}, {%0,%1,%2,%3};"
                        : "+f"(acc[mt][nt][0]), "+f"(acc[mt][nt][1]),
                          "+f"(acc[mt][nt][2]), "+f"(acc[mt][nt][3])
                        : "r"(af[mt][0]), "r"(af[mt][1]), "r"(af[mt][2]), "r"(af[mt][3]),
                          "r"(bf[nt][0]), "r"(bf[nt][1]));
                }
        }
    }

#pragma unroll
    for (int mt = 0; mt < 2; mt++) {
        const int r0 = m0 + wm + mt * 16 + g;
        const int r1 = r0 + 8;
        const bool ok0 = r0 < R, ok1 = r1 < R;
        const int bi0 = ok0 ? (r0 / rows_per_b) : 0;
        const int bi1 = ok1 ? (r1 / rows_per_b) : 0;
        float p0 = 0.f, p1 = 0.f;
#pragma unroll
        for (int nt = 0; nt < 8; nt++) {
            const int n = n0 + wn + nt * 8 + tig * 2;
            const float v0 = v[n], v1 = v[n + 1];
            p0 = fmaf(v0, tanhf(acc[mt][nt][0] + Cb[(size_t)bi0 * Hd + n]), p0);
            p0 = fmaf(v1, tanhf(acc[mt][nt][1] + Cb[(size_t)bi0 * Hd + n + 1]), p0);
            p1 = fmaf(v0, tanhf(acc[mt][nt][2] + Cb[(size_t)bi1 * Hd + n]), p1);
            p1 = fmaf(v1, tanhf(acc[mt][nt][3] + Cb[(size_t)bi1 * Hd + n + 1]), p1);
        }
        p0 += __shfl_xor_sync(0xffffffffu, p0, 1);
        p0 += __shfl_xor_sync(0xffffffffu, p0, 2);
        p1 += __shfl_xor_sync(0xffffffffu, p1, 1);
        p1 += __shfl_xor_sync(0xffffffffu, p1, 2);
        if (tig == 0) {
            if (ok0) atomicAdd(&outp[r0], p0);
            if (ok1) atomicAdd(&outp[r1], p1);
        }
    }
}

// =================================================================================
// node_fused: all four preact dots + gating in one kernel.
//   warp -> 1 column n, 16 rows; block = 8 warps -> 2 columns x 64 rows.
//   A row = [left_childs | cur_emb] built inline.  grid.x = 512.
// =================================================================================
__global__ __launch_bounds__(256) void node_fused(
    const float* __restrict__ cur_emb, const float* __restrict__ left_childs,
    const float* __restrict__ Wl, const float* __restrict__ Wlg,
    const float* __restrict__ Wr, const float* __restrict__ Wrg,
    const float* __restrict__ bl, const float* __restrict__ blg,
    const float* __restrict__ br, const float* __restrict__ brg,
    const unsigned char* __restrict__ lm, float* __restrict__ o_node)
{
    __shared__ __align__(16) float As[64][128];   // 32 KB chunk of [lc | cur]
    __shared__ int smode;
    const int tid = threadIdx.x, warp = tid >> 5, lane = tid & 31;
    const int n = blockIdx.x * 2 + (warp & 1);
    const int r0 = (warp >> 1) * 16;

    if (tid == 0) {
        int mode = 0;  // 0=int32, 1=bool8, 2=float32
        bool nonalign = false;
        for (int t = 1; t < 64; t++)
            if ((t & 3) && lm[t]) { nonalign = true; break; }
        if (nonalign) {
            const unsigned int* w = (const unsigned int*)lm;
            bool isf = true;
            for (int t = 0; t < 16; t++) {
                unsigned int x = w[t];
                if (x != 0u && x != 0x3F800000u) { isf = false; break; }
            }
            mode = isf ? 2 : 1;
        }
        smode = mode;
    }

    float al[16], alg[16], ar[16], arg[16];
#pragma unroll
    for (int r = 0; r < 16; r++) { al[r] = 0.f; alg[r] = 0.f; ar[r] = 0.f; arg[r] = 0.f; }

    for (int kc = 0; kc < 2 * Hd; kc += 128) {
        const bool second = kc >= Hd;                 // chunk boundary aligns with Hd
        const float* src = second ? cur_emb : left_childs;
        const int base = second ? (kc - Hd) : kc;
        __syncthreads();
#pragma unroll
        for (int it = 0; it < 8; it++) {
            int idx = tid + it * 256;
            int r = idx >> 5, c4 = idx & 31;
            *(float4*)&As[r][c4 * 4] =
                *(const float4*)(src + (size_t)r * Hd + base + c4 * 4);
        }
        __syncthreads();
        const int gc = kc + lane * 4;
        float4 wr_ = *(const float4*)(Wr + (size_t)n * 2048 + gc);
        float4 wrg_ = *(const float4*)(Wrg + (size_t)n * 2048 + gc);
        float4 wl_ = make_float4(0.f, 0.f, 0.f, 0.f), wlg_ = wl_;
        if (second) {
            wl_ = *(const float4*)(Wl + (size_t)n * Hd + gc - Hd);
            wlg_ = *(const float4*)(Wlg + (size_t)n * Hd + gc - Hd);
        }
#pragma unroll
        for (int r = 0; r < 16; r++) {
            float4 a = *(const float4*)&As[r0 + r][lane * 4];
            ar[r]  = fmaf(wr_.x, a.x, fmaf(wr_.y, a.y, fmaf(wr_.z, a.z, fmaf(wr_.w, a.w, ar[r]))));
            arg[r] = fmaf(wrg_.x, a.x, fmaf(wrg_.y, a.y, fmaf(wrg_.z, a.z, fmaf(wrg_.w, a.w, arg[r]))));
            if (second) {
                al[r]  = fmaf(wl_.x, a.x, fmaf(wl_.y, a.y, fmaf(wl_.z, a.z, fmaf(wl_.w, a.w, al[r]))));
                alg[r] = fmaf(wlg_.x, a.x, fmaf(wlg_.y, a.y, fmaf(wlg_.z, a.z, fmaf(wlg_.w, a.w, alg[r]))));
            }
        }
    }
#pragma unroll
    for (int off = 16; off; off >>= 1)
#pragma unroll
        for (int r = 0; r < 16; r++) {
            al[r]  += __shfl_xor_sync(0xffffffffu, al[r], off);
            alg[r] += __shfl_xor_sync(0xffffffffu, alg[r], off);
            ar[r]  += __shfl_xor_sync(0xffffffffu, ar[r], off);
            arg[r] += __shfl_xor_sync(0xffffffffu, arg[r], off);
        }

    const float bl_ = bl[n], blg_ = blg[n], br_ = br[n], brg_ = brg[n];
    const int mode = smode;
#pragma unroll
    for (int r = 0; r < 16; r++) {
        if (lane == r) {
            const int b = r0 + r;
            bool m;
            if (mode == 1)      m = lm[b] != 0;
            else if (mode == 2) m = ((const float*)lm)[b] != 0.f;
            else                 m = ((const int*)lm)[b] != 0;
            float lv = tanhf(al[r] + bl_) * (1.f / (1.f + expf(-(alg[r] + blg_))));
            float rv = tanhf(ar[r] + br_) * (1.f / (1.f + expf(-(arg[r] + brg_))));
            float nv = m ? rv : lv;
            g_node[(size_t)b * Hd + n] = nv;
            o_node[(size_t)b * Hd + n] = nv;
            g_cat[(size_t)b * 2 * Hd + n] = nv;
        }
    }
}

// =================================================================================
// Skinny GEMM v2 (cnode / leaf / score biases)
// =================================================================================
struct SkJob {
    const float* A;
    const float* W;
    const float* bias;
    float* out;
    int lda, ldw, K, act;
};
struct SkJobs { SkJob j[4]; };

#define SK_CHUNK 128

__global__ __launch_bounds__(256) void skinny_gemm(SkJobs jobs) {
    const SkJob jb = jobs.j[blockIdx.y];
    __shared__ __align__(16) float As[64][SK_CHUNK];
    const int tid = threadIdx.x, warp = tid >> 5, lane = tid & 31;
    const int nb = blockIdx.x * 8 + (warp & 1) * 4;
    const int r0 = (warp >> 1) * 16;

    const float* w0 = jb.W + (size_t)(nb + 0) * jb.ldw;
    const float* w1 = jb.W + (size_t)(nb + 1) * jb.ldw;
    const float* w2 = jb.W + (size_t)(nb + 2) * jb.ldw;
    const float* w3 = jb.W + (size_t)(nb + 3) * jb.ldw;

    float acc[4][16];
#pragma unroll
    for (int c = 0; c < 4; c++)
#pragma unroll
        for (int r = 0; r < 16; r++) acc[c][r] = 0.f;

    for (int kc = 0; kc < jb.K; kc += SK_CHUNK) {
        __syncthreads();
#pragma unroll
        for (int it = 0; it < 8; it++) {
            int idx = tid + it * 256;
            int r = idx >> 5, cc = idx & 31;
            *(float4*)&As[r][cc * 4] =
                *(const float4*)(jb.A + (size_t)r * jb.lda + kc + cc * 4);
        }
        __syncthreads();
        const int ko = kc + lane * 4;
        float4 wv0 = *(const float4*)(w0 + ko);
        float4 wv1 = *(const float4*)(w1 + ko);
        float4 wv2 = *(const float4*)(w2 + ko);
        float4 wv3 = *(const float4*)(w3 + ko);
#pragma unroll
        for (int r = 0; r < 16; r++) {
            float4 a = *(const float4*)&As[r0 + r][lane * 4];
            acc[0][r] = fmaf(wv0.x, a.x, fmaf(wv0.y, a.y, fmaf(wv0.z, a.z, fmaf(wv0.w, a.w, acc[0][r]))));
            acc[1][r] = fmaf(wv1.x, a.x, fmaf(wv1.y, a.y, fmaf(wv1.z, a.z, fmaf(wv1.w, a.w, acc[1][r]))));
            acc[2][r] = fmaf(wv2.x, a.x, fmaf(wv2.y, a.y, fmaf(wv2.z, a.z, fmaf(wv2.w, a.w, acc[2][r]))));
            acc[3][r] = fmaf(wv3.x, a.x, fmaf(wv3.y, a.y, fmaf(wv3.z, a.z, fmaf(wv3.w, a.w, acc[3][r]))));
        }
    }
#pragma unroll
    for (int off = 16; off; off >>= 1)
#pragma unroll
        for (int c = 0; c < 4; c++)
#pragma unroll
            for (int r = 0; r < 16; r++)
                acc[c][r] += __shfl_xor_sync(0xffffffffu, acc[c][r], off);

    float bv0 = jb.bias[nb + 0], bv1 = jb.bias[nb + 1];
    float bv2 = jb.bias[nb + 2], bv3 = jb.bias[nb + 3];
#pragma unroll
    for (int r = 0; r < 16; r++) {
        if (lane == r) {
            float o0 = acc[0][r] + bv0, o1 = acc[1][r] + bv1;
            float o2 = acc[2][r] + bv2, o3 = acc[3][r] + bv3;
            if (jb.act == 1) { o0 = tanhf(o0); o1 = tanhf(o1); o2 = tanhf(o2); o3 = tanhf(o3); }
            float* op = jb.out + (size_t)(r0 + r) * Hd + nb;
            op[0] = o0; op[1] = o1; op[2] = o2; op[3] = o3;
        }
    }
}

// ---------------- small kernels ----------------
__global__ void init_kernel(const float* __restrict__ bs) {
    int i = blockIdx.x * blockDim.x + threadIdx.x;
    if (i < Bd * Sd) { g_energy[i] = bs[0]; return; }
    i -= Bd * Sd;
    if (i < Bd * (NTOT + OPd)) g_spre[i] = 0.f;
}

__global__ void softmax_kernel(const int* __restrict__ seq_mask) {
    int b = blockIdx.x, s = threadIdx.x;
    __shared__ float red[Sd];
    float val = g_energy[b * Sd + s];
    if (seq_mask[b * Sd + s] == 0) val = NEGV;
    red[s] = val; __syncthreads();
    for (int off = Sd / 2; off > 0; off >>= 1) {
        if (s < off) red[s] = fmaxf(red[s], red[s + off]);
        __syncthreads();
    }
    float mx = red[0]; __syncthreads();
    float ex = expf(val - mx);
    red[s] = ex; __syncthreads();
    for (int off = Sd / 2; off > 0; off >>= 1) {
        if (s < off) red[s] += red[s + off];
        __syncthreads();
    }
    g_energy[b * Sd + s] = ex / red[0];
}

__global__ void ctx_kernel(float* o_ctx) {
    int b = blockIdx.x;
    int h = blockIdx.y * 128 + threadIdx.x;
    __shared__ float aw[Sd];
    for (int i = threadIdx.x; i < Sd; i += 128) aw[i] = g_energy[b * Sd + i];
    __syncthreads();
    const __half* ep = g_ench + (size_t)b * Sd * Hd + h;
    float s0 = 0.f;
#pragma unroll 4
    for (int t = 0; t < Sd; t++)
        s0 = fmaf(aw[t], __half2float(ep[(size_t)t * Hd]), s0);
    o_ctx[b * Hd + h] = s0;
    g_cat[(size_t)b * 2 * Hd + Hd + h] = s0;
}

__global__ void constnum_kernel(const float* __restrict__ cemb,
                                const float* __restrict__ pades, float* o_cn) {
    int i = blockIdx.x * blockDim.x + threadIdx.x;
    if (i >= Bd * NTOT * Hd) return;
    int h = i & (Hd - 1);
    int rn = i >> 10;
    int n = rn % NTOT, b = rn / NTOT;
    o_cn[i] = (n < NCd) ? cemb[n * Hd + h]
                        : pades[((size_t)b * NNd + (n - NCd)) * Hd + h];
}

__global__ void fin_kernel(const int* __restrict__ mask_nums, float* o_num, float* o_op) {
    int i = blockIdx.x * blockDim.x + threadIdx.x;
    if (i < Bd * NTOT) o_num[i] = mask_nums[i] ? g_spre[i] : NEGV;
    if (i < Bd * OPd)  o_op[i]  = g_spre[Bd * NTOT + i];
}

// ---------------- launch ----------------
extern "C" void kernel_launch(void* const* d_in, const int* in_sizes, int n_in,
                              void* d_out, int out_size)
{
    const float* cur_emb     = (const float*)d_in[0];
    const float* left_childs = (const float*)d_in[1];
    const unsigned char* left_mask = (const unsigned char*)d_in[2];
    const float* enc         = (const float*)d_in[3];
    const float* num_pades   = (const float*)d_in[4];
    const int*   seq_mask    = (const int*)d_in[5];
    const int*   mask_nums   = (const int*)d_in[6];
    const float* cemb        = (const float*)d_in[7];
    const float* opemb       = (const float*)d_in[8];
    const float* Wl   = (const float*)d_in[9];
    const float* bl   = (const float*)d_in[10];
    const float* Wlg  = (const float*)d_in[11];
    const float* blg  = (const float*)d_in[12];
    const float* Wr   = (const float*)d_in[13];
    const float* br   = (const float*)d_in[14];
    const float* Wrg  = (const float*)d_in[15];
    const float* brg  = (const float*)d_in[16];
    const float* Wleaf= (const float*)d_in[17];
    const float* bleaf= (const float*)d_in[18];
    const float* Wa   = (const float*)d_in[19];
    const float* ba   = (const float*)d_in[20];
    const float* Ws   = (const float*)d_in[21];
    const float* bs   = (const float*)d_in[22];
    const float* Wna  = (const float*)d_in[23];
    const float* bna  = (const float*)d_in[24];
    const float* Wns  = (const float*)d_in[25];
    const float* Woa  = (const float*)d_in[26];
    const float* boa  = (const float*)d_in[27];
    const float* Wos  = (const float*)d_in[28];

    float* out   = (float*)d_out;
    float* o_num = out;
    float* o_op  = out + 2240;
    float* o_node= out + 2560;
    float* o_ctx = out + 68096;
    float* o_cn  = out + 133632;
    float* o_ope = out + 2427392;

    void* p;
    cudaGetSymbolAddress(&p, g_node);    float* node_   = (float*)p;
    cudaGetSymbolAddress(&p, g_cnode);   float* cnode_  = (float*)p;
    cudaGetSymbolAddress(&p, g_energy);  float* energy_ = (float*)p;
    cudaGetSymbolAddress(&p, g_cat);     float* cat_    = (float*)p;
    cudaGetSymbolAddress(&p, g_leaf);    float* leaf_   = (float*)p;
    cudaGetSymbolAddress(&p, g_cnum);    float* cnum_   = (float*)p;
    cudaGetSymbolAddress(&p, g_cop);     float* cop_    = (float*)p;
    cudaGetSymbolAddress(&p, g_spre);    float* spre_   = (float*)p;
    cudaGetSymbolAddress(&p, g_ench);    __half* ench_  = (__half*)p;
    cudaGetSymbolAddress(&p, g_wah);     __half* wah_   = (__half*)p;
    cudaGetSymbolAddress(&p, g_wnah);    __half* wnah_  = (__half*)p;
    cudaGetSymbolAddress(&p, g_woah);    __half* woah_  = (__half*)p;
    cudaGetSymbolAddress(&p, g_aexth);   __half* aexth_ = (__half*)p;

    cudaFuncSetAttribute(mma_energy256, cudaFuncAttributeMaxDynamicSharedMemorySize, ESMEM);
    cudaFuncSetAttribute(mma_f16_score, cudaFuncAttributeMaxDynamicSharedMemorySize, SSMEM);

    // side streams + events (created once; host objects, no device allocation)
    static cudaStream_t s1 = nullptr, s2 = nullptr;
    static cudaEvent_t evFork = nullptr, evCvt = nullptr, evAux = nullptr;
    static cudaEvent_t evPrep = nullptr, evOp = nullptr;
    static cudaEvent_t evLeaf = nullptr, evBias = nullptr;
    if (!s1) {
        cudaStreamCreateWithFlags(&s1, cudaStreamNonBlocking);
        cudaStreamCreateWithFlags(&s2, cudaStreamNonBlocking);
        cudaEventCreateWithFlags(&evFork, cudaEventDisableTiming);
        cudaEventCreateWithFlags(&evCvt, cudaEventDisableTiming);
        cudaEventCreateWithFlags(&evAux, cudaEventDisableTiming);
        cudaEventCreateWithFlags(&evPrep, cudaEventDisableTiming);
        cudaEventCreateWithFlags(&evOp, cudaEventDisableTiming);
        cudaEventCreateWithFlags(&evLeaf, cudaEventDisableTiming);
        cudaEventCreateWithFlags(&evBias, cudaEventDisableTiming);
    }

    // fork
    cudaEventRecord(evFork, 0);
    cudaStreamWaitEvent(s1, evFork, 0);
    cudaStreamWaitEvent(s2, evFork, 0);

    // s1: enc + Wa fp16 convert (gates energies only)
    {
        int tot4 = (32768 * 1024 + 1024 * 1024) / 4;
        cvt_enc_kernel<<<(tot4 + 255) / 256, 256, 0, s1>>>(enc, Wa);
        cudaEventRecord(evCvt, s1);
    }

    // s2: Wna/Woa convert + const_num + emb-half A rows + opemb copy
    {
        int tot4 = (2 * 1024 * 2048) / 4;
        cvt_w_kernel<<<(tot4 + 255) / 256, 256, 0, s2>>>(Wna, Woa);
    }
    constnum_kernel<<<(Bd * NTOT * Hd + 255) / 256, 256, 0, s2>>>(cemb, num_pades, o_cn);
    prep_emb<<<(2560 * 1024 + 255) / 256, 256, 0, s2>>>(o_cn, opemb);
    cudaMemcpyAsync(o_ope, opemb, OPd * Hd * sizeof(float), cudaMemcpyDeviceToDevice, s2);
    cudaEventRecord(evAux, s2);

    // s0: tiny init + fused node chain
    {
        int total = Bd * Sd + Bd * (NTOT + OPd);
        init_kernel<<<(total + 255) / 256, 256>>>(bs);
    }
    node_fused<<<512, 256>>>(cur_emb, left_childs, Wl, Wlg, Wr, Wrg,
                             bl, blg, br, brg, left_mask, o_node);
    {
        SkJobs js;
        js.j[0] = { node_, Wa, ba, cnode_, Hd, 2 * Hd, Hd, 0 };
        skinny_gemm<<<dim3(128, 1), 256>>>(js);
    }

    // join cvt, energies single launch -> softmax -> ctx
    cudaStreamWaitEvent(0, evCvt, 0);
    mma_energy256<<<dim3(8, 256), 256, ESMEM>>>(ench_, wah_, cnode_, Ws, energy_);
    softmax_kernel<<<Bd, Sd>>>(seq_mask);
    dim3 gctx(Bd, 8);
    ctx_kernel<<<gctx, 128>>>(o_ctx);

    // leaf
    {
        SkJobs js;
        js.j[0] = { cat_, Wleaf, bleaf, leaf_, 2 * Hd, 2 * Hd, 2 * Hd, 1 };
        skinny_gemm<<<dim3(128, 1), 256>>>(js);
    }
    cudaEventRecord(evLeaf, 0);

    // s1: per-batch score biases, concurrent with prep_leafemb on s0
    cudaStreamWaitEvent(s1, evLeaf, 0);
    {
        SkJobs js;
        js.j[0] = { leaf_, Wna, bna, cnum_, Hd, 3 * Hd, Hd, 0 };
        js.j[1] = { leaf_, Woa, boa, cop_,  Hd, 3 * Hd, Hd, 0 };
        skinny_gemm<<<dim3(128, 2), 256, 0, s1>>>(js);
    }
    cudaEventRecord(evBias, s1);

    // s0: leaf-half of A rows (needs s2's emb half done)
    cudaStreamWaitEvent(0, evAux, 0);
    prep_leafemb<<<(2560 * 1024 + 255) / 256, 256>>>(o_cn, opemb);
    cudaEventRecord(evPrep, 0);

    // num head on s0 (needs biases), op head concurrently on s1
    cudaStreamWaitEvent(0, evBias, 0);
    mma_f16_score<<<dim3(8, 35), 128, SSMEM>>>(aexth_, wnah_, cnum_, Wns, spre_,
                                               Bd * NTOT, NTOT, 2 * Hd);
    cudaStreamWaitEvent(s1, evPrep, 0);
    mma_f16_score<<<dim3(8, 5), 128, SSMEM, s1>>>(
        aexth_ + (size_t)Bd * NTOT * 2 * Hd, woah_, cop_, Wos, spre_ + Bd * NTOT,
        Bd * OPd, OPd, 2 * Hd);
    cudaEventRecord(evOp, s1);
    cudaStreamWaitEvent(0, evOp, 0);

    fin_kernel<<<(Bd * NTOT + 255) / 256, 256>>>(mask_nums, o_num, o_op);
}

// round 17
// speedup vs baseline: 1.0369x; 1.0369x over previous
#include <cuda_runtime.h>
#include <cuda_bf16.h>
#include <cuda_fp16.h>
#include <cstdint>

#define Hd 1024
#define Bd 64
#define Sd 512
#define NCd 20
#define NNd 15
#define OPd 5
#define NTOT 35
#define NEGV (-1e12f)

// ---------------- scratch (device globals; no allocation allowed) ----------------
__device__ float g_pre[4 * Bd * Hd];
__device__ float g_lc[Bd * 2 * Hd];
__device__ float g_node[Bd * Hd];
__device__ float g_cnode[Bd * Hd];
__device__ float g_energy[Bd * Sd];
__device__ float g_cat[Bd * 2 * Hd];
__device__ float g_leaf[Bd * Hd];
__device__ float g_cnum[Bd * Hd];
__device__ float g_cop[Bd * Hd];
__device__ float g_spre[Bd * NTOT + Bd * OPd];
__device__ __half g_ench[32768 * 1024];          // enc fp16 (64 MB)
__device__ __half g_wah[1024 * 1024];            // Wa[:, Hd:2Hd] fp16
__device__ __half g_wnah[1024 * 2048];           // Wna[:, Hd:3Hd] fp16
__device__ __half g_woah[1024 * 2048];           // Woa[:, Hd:3Hd] fp16
__device__ __half g_aexth[2560 * 2048];          // [emb | leaf*emb] fp16 rows

// ================= helpers =================
__device__ __forceinline__ uint32_t smem_u32(const void* p) {
    uint32_t a;
    asm("{ .reg .u64 t; cvta.to.shared.u64 t, %1; cvt.u32.u64 %0, t; }" : "=r"(a) : "l"(p));
    return a;
}
__device__ __forceinline__ void cpasync16(uint32_t saddr, const void* g) {
    asm volatile("cp.async.cg.shared.global [%0], [%1], 16;" :: "r"(saddr), "l"(g));
}
#define CP_COMMIT() asm volatile("cp.async.commit_group;" ::: "memory")
#define CP_WAIT2()  asm volatile("cp.async.wait_group 2;" ::: "memory")
#define CP_WAIT1()  asm volatile("cp.async.wait_group 1;" ::: "memory")
#define CP_WAIT0()  asm volatile("cp.async.wait_group 0;" ::: "memory")

// ---------------- fp32 -> fp16 convert pre-passes ----------------
__device__ __forceinline__ void cvt_store4(__half* dst, float4 a) {
    __half2 h0 = __floats2half2_rn(a.x, a.y);
    __half2 h1 = __floats2half2_rn(a.z, a.w);
    uint2 u;
    u.x = *(uint32_t*)&h0; u.y = *(uint32_t*)&h1;
    *(uint2*)dst = u;
}
__global__ void cvt_enc_kernel(const float* __restrict__ enc, const float* __restrict__ Wa) {
    const int EN4 = (32768 * 1024) / 4;
    int i = blockIdx.x * blockDim.x + threadIdx.x;
    if (i < EN4) {
        cvt_store4(g_ench + (size_t)i * 4, ((const float4*)enc)[i]);
        return;
    }
    i -= EN4;
    if (i < (1024 * 1024) / 4) {
        int n = i >> 8, c = i & 255;
        cvt_store4(g_wah + (size_t)n * 1024 + c * 4,
                   *(const float4*)(Wa + (size_t)n * 2048 + 1024 + c * 4));
    }
}
__global__ void cvt_w_kernel(const float* __restrict__ Wna, const float* __restrict__ Woa) {
    const int WX4 = (1024 * 2048) / 4;
    int i = blockIdx.x * blockDim.x + threadIdx.x;
    if (i < WX4) {
        int n = i >> 9, c = i & 511;
        cvt_store4(g_wnah + (size_t)n * 2048 + c * 4,
                   *(const float4*)(Wna + (size_t)n * 3072 + 1024 + c * 4));
        return;
    }
    i -= WX4;
    if (i < WX4) {
        int n = i >> 9, c = i & 511;
        cvt_store4(g_woah + (size_t)n * 2048 + c * 4,
                   *(const float4*)(Woa + (size_t)n * 3072 + 1024 + c * 4));
    }
}

// ---------------- fp16 A-rows for score heads, split halves ----------------
__global__ void prep_emb(const float* __restrict__ ocn, const float* __restrict__ opemb) {
    int i = blockIdx.x * blockDim.x + threadIdx.x;
    if (i >= 2560 * 1024) return;
    int r = i >> 10, h = i & (Hd - 1);
    float e;
    if (r < Bd * NTOT) e = ocn[(size_t)r * Hd + h];
    else {
        int rr = r - Bd * NTOT;
        e = opemb[(size_t)(rr % OPd) * Hd + h];
    }
    g_aexth[(size_t)r * 2048 + h] = __float2half(e);
}
__global__ void prep_leafemb(const float* __restrict__ ocn, const float* __restrict__ opemb) {
    int i = blockIdx.x * blockDim.x + threadIdx.x;
    if (i >= 2560 * 1024) return;
    int r = i >> 10, h = i & (Hd - 1);
    float e;
    int b;
    if (r < Bd * NTOT) { b = r / NTOT; e = ocn[(size_t)r * Hd + h]; }
    else {
        int rr = r - Bd * NTOT;
        b = rr / OPd;
        e = opemb[(size_t)(rr % OPd) * Hd + h];
    }
    g_aexth[(size_t)r * 2048 + Hd + h] = __float2half(e * g_leaf[(size_t)b * Hd + h]);
}

#define FP2 20

// =================================================================================
// Energies GEMM: 256 threads, 8 warps (4x2), warp tile 32x64, CTA 128x128,
// 4-stage cp.async, ldmatrix, 2 CTA/SM.
// =================================================================================
#define ESTG ((128 + 128) * FP2)
#define ESMEM (4 * ESTG * 4)

__global__ __launch_bounds__(256, 2) void mma_energy256(
    const __half* __restrict__ Ah, const __half* __restrict__ Bh,
    const float* __restrict__ Cb, const float* __restrict__ v,
    float* __restrict__ outp)
{
    extern __shared__ __align__(16) uint32_t fsm[];
    const int tid = threadIdx.x;
    const int n0 = blockIdx.x * 128;
    const int m0 = blockIdx.y * 128;
    const int warp = tid >> 5, lane = tid & 31;
    const int g = lane >> 2, tig = lane & 3;
    const int wm = (warp & 3) * 32;
    const int wn = (warp >> 2) * 64;
    const uint32_t sbase = smem_u32(fsm);

    const int aro = (lane & 7) | (lane & 8);
    const int aco = (lane & 16) ? 4 : 0;
    const int bro = (lane & 7) | ((lane & 16) >> 1);
    const int bco = (lane & 8) >> 1;

    float acc[2][8][4];
#pragma unroll
    for (int mt = 0; mt < 2; mt++)
#pragma unroll
        for (int nt = 0; nt < 8; nt++)
#pragma unroll
            for (int c = 0; c < 4; c++) acc[mt][nt][c] = 0.f;

#define EPF(c_) do {                                                              \
    const uint32_t _sb = sbase + (uint32_t)((c_) & 3) * (ESTG * 4);               \
    const int _k0 = (c_) * 32;                                                    \
    _Pragma("unroll")                                                             \
    for (int it = 0; it < 2; it++) {                                              \
        int idx = tid + it * 256; int r = idx >> 2, pp = idx & 3;                 \
        cpasync16(_sb + (uint32_t)(r * FP2 + pp * 4) * 4,                         \
                  Ah + (size_t)(m0 + r) * 1024 + _k0 + pp * 8);                   \
    }                                                                             \
    _Pragma("unroll")                                                             \
    for (int it = 0; it < 2; it++) {                                              \
        int idx = tid + it * 256; int r = idx >> 2, pp = idx & 3;                 \
        cpasync16(_sb + (uint32_t)((128 * FP2 + r * FP2 + pp * 4)) * 4,           \
                  Bh + (size_t)(n0 + r) * 1024 + _k0 + pp * 8);                   \
    }                                                                             \
    CP_COMMIT();                                                                  \
} while (0)

    EPF(0); EPF(1); EPF(2);

    for (int c = 0; c < 32; c++) {
        const int rem = 31 - c;
        if (rem >= 2) CP_WAIT2(); else if (rem == 1) CP_WAIT1(); else CP_WAIT0();
        __syncthreads();
        if (c + 3 < 32) EPF(c + 3);

        const uint32_t stg = sbase + (uint32_t)(c & 3) * (ESTG * 4);

#pragma unroll
        for (int kk = 0; kk < 2; kk++) {
            uint32_t af[2][4];
#pragma unroll
            for (int mt = 0; mt < 2; mt++) {
                uint32_t aaddr = stg +
                    (uint32_t)(((wm + mt * 16 + aro) * FP2 + kk * 8 + aco) * 4);
                asm volatile(
                    "ldmatrix.sync.aligned.m8n8.x4.shared.b16 {%0,%1,%2,%3}, [%4];"
                    : "=r"(af[mt][0]), "=r"(af[mt][1]), "=r"(af[mt][2]), "=r"(af[mt][3])
                    : "r"(aaddr));
            }
            uint32_t bf[8][2];
#pragma unroll
            for (int p = 0; p < 4; p++) {
                uint32_t baddr = stg +
                    (uint32_t)((128 * FP2 + (wn + p * 16 + bro) * FP2 + kk * 8 + bco) * 4);
                asm volatile(
                    "ldmatrix.sync.aligned.m8n8.x4.shared.b16 {%0,%1,%2,%3}, [%4];"
                    : "=r"(bf[2 * p][0]), "=r"(bf[2 * p][1]),
                      "=r"(bf[2 * p + 1][0]), "=r"(bf[2 * p + 1][1])
                    : "r"(baddr));
            }
#pragma unroll
            for (int mt = 0; mt < 2; mt++)
#pragma unroll
                for (int nt = 0; nt < 8; nt++) {
                    asm volatile(
                        "mma.sync.aligned.m16n8k16.row.col.f32.f16.f16.f32 "
                        "{%0,%1,%2,%3}, {%4,%5,%6,%7}, {%8,%9}, {%0,%1,%2,%3};"
                        : "+f"(acc[mt][nt][0]), "+f"(acc[mt][nt][1]),
                          "+f"(acc[mt][nt][2]), "+f"(acc[mt][nt][3])
                        : "r"(af[mt][0]), "r"(af[mt][1]), "r"(af[mt][2]), "r"(af[mt][3]),
                          "r"(bf[nt][0]), "r"(bf[nt][1]));
                }
        }
    }

#pragma unroll
    for (int mt = 0; mt < 2; mt++) {
        const int r0 = m0 + wm + mt * 16 + g;
        const int r1 = r0 + 8;
        const int bi0 = r0 >> 9;
        const int bi1 = r1 >> 9;
        float p0 = 0.f, p1 = 0.f;
#pragma unroll
        for (int nt = 0; nt < 8; nt++) {
            const int n = n0 + wn + nt * 8 + tig * 2;
            const float v0 = v[n], v1 = v[n + 1];
            p0 = fmaf(v0, tanhf(acc[mt][nt][0] + Cb[(size_t)bi0 * Hd + n]), p0);
            p0 = fmaf(v1, tanhf(acc[mt][nt][1] + Cb[(size_t)bi0 * Hd + n + 1]), p0);
            p1 = fmaf(v0, tanhf(acc[mt][nt][2] + Cb[(size_t)bi1 * Hd + n]), p1);
            p1 = fmaf(v1, tanhf(acc[mt][nt][3] + Cb[(size_t)bi1 * Hd + n + 1]), p1);
        }
        p0 += __shfl_xor_sync(0xffffffffu, p0, 1);
        p0 += __shfl_xor_sync(0xffffffffu, p0, 2);
        p1 += __shfl_xor_sync(0xffffffffu, p1, 1);
        p1 += __shfl_xor_sync(0xffffffffu, p1, 2);
        if (tig == 0) {
            atomicAdd(&outp[r0], p0);
            atomicAdd(&outp[r1], p1);
        }
    }
}

// =================================================================================
// Score-head GEMM: 128 threads, CTA 64x128, warp tile 32x64
// =================================================================================
#define SSTG ((64 + 128) * FP2)
#define SSMEM (4 * SSTG * 4)

__global__ __launch_bounds__(128) void mma_f16_score(
    const __half* __restrict__ Ah, const __half* __restrict__ Bh,
    const float* __restrict__ Cb, const float* __restrict__ v,
    float* __restrict__ outp, int R, int rows_per_b, int K)
{
    extern __shared__ __align__(16) uint32_t fsm[];
    const int tid = threadIdx.x;
    const int n0 = blockIdx.x * 128;
    const int m0 = blockIdx.y * 64;
    const int warp = tid >> 5, lane = tid & 31;
    const int g = lane >> 2, tig = lane & 3;
    const int wm = (warp & 1) * 32;
    const int wn = (warp >> 1) * 64;
    const uint32_t sbase = smem_u32(fsm);
    const int nch = K >> 5;

    const int aro = (lane & 7) | (lane & 8);
    const int aco = (lane & 16) ? 4 : 0;
    const int bro = (lane & 7) | ((lane & 16) >> 1);
    const int bco = (lane & 8) >> 1;

    float acc[2][8][4];
#pragma unroll
    for (int mt = 0; mt < 2; mt++)
#pragma unroll
        for (int nt = 0; nt < 8; nt++)
#pragma unroll
            for (int c = 0; c < 4; c++) acc[mt][nt][c] = 0.f;

    auto prefetch = [&](int c_) {
        const uint32_t _sb = sbase + (uint32_t)(c_ & 3) * (SSTG * 4);
        const int _k0 = c_ * 32;
#pragma unroll
        for (int it = 0; it < 2; it++) {
            int idx = tid + it * 128; int r = idx >> 2, pp = idx & 3;
            int gr = m0 + r; if (gr >= R) gr = R - 1;
            cpasync16(_sb + (uint32_t)(r * FP2 + pp * 4) * 4,
                      Ah + (size_t)gr * K + _k0 + pp * 8);
        }
#pragma unroll
        for (int it = 0; it < 4; it++) {
            int idx = tid + it * 128; int r = idx >> 2, pp = idx & 3;
            cpasync16(_sb + (uint32_t)((64 * FP2 + r * FP2 + pp * 4)) * 4,
                      Bh + (size_t)(n0 + r) * K + _k0 + pp * 8);
        }
        CP_COMMIT();
    };

    prefetch(0); prefetch(1); prefetch(2);

    for (int c = 0; c < nch; c++) {
        const int rem = nch - 1 - c;
        if (rem >= 2) CP_WAIT2(); else if (rem == 1) CP_WAIT1(); else CP_WAIT0();
        __syncthreads();
        if (c + 3 < nch) prefetch(c + 3);

        const uint32_t stg = sbase + (uint32_t)(c & 3) * (SSTG * 4);

#pragma unroll
        for (int kk = 0; kk < 2; kk++) {
            uint32_t af[2][4];
#pragma unroll
            for (int mt = 0; mt < 2; mt++) {
                uint32_t aaddr = stg +
                    (uint32_t)(((wm + mt * 16 + aro) * FP2 + kk * 8 + aco) * 4);
                asm volatile(
                    "ldmatrix.sync.aligned.m8n8.x4.shared.b16 {%0,%1,%2,%3}, [%4];"
                    : "=r"(af[mt][0]), "=r"(af[mt][1]), "=r"(af[mt][2]), "=r"(af[mt][3])
                    : "r"(aaddr));
            }
            uint32_t bf[8][2];
#pragma unroll
            for (int p = 0; p < 4; p++) {
                uint32_t baddr = stg +
                    (uint32_t)((64 * FP2 + (wn + p * 16 + bro) * FP2 + kk * 8 + bco) * 4);
                asm volatile(
                    "ldmatrix.sync.aligned.m8n8.x4.shared.b16 {%0,%1,%2,%3}, [%4];"
                    : "=r"(bf[2 * p][0]), "=r"(bf[2 * p][1]),
                      "=r"(bf[2 * p + 1][0]), "=r"(bf[2 * p + 1][1])
                    : "r"(baddr));
            }
#pragma unroll
            for (int mt = 0; mt < 2; mt++)
#pragma unroll
                for (int nt = 0; nt < 8; nt++) {
                    asm volatile(
                        "mma.sync.aligned.m16n8k16.row.col.f32.f16.f16.f32 "
                        "{%0,%1,%2,%3}, {%4,%5,%6,%7}, {%8,%9}, {%0,%1,%2,%3};"
                        : "+f"(acc[mt][nt][0]), "+f"(acc[mt][nt][1]),
                          "+f"(acc[mt][nt][2]), "+f"(acc[mt][nt][3])
                        : "r"(af[mt][0]), "r"(af[mt][1]), "r"(af[mt][2]), "r"(af[mt][3]),
                          "r"(bf[nt][0]), "r"(bf[nt][1]));
                }
        }
    }

#pragma unroll
    for (int mt = 0; mt < 2; mt++) {
        const int r0 = m0 + wm + mt * 16 + g;
        const int r1 = r0 + 8;
        const bool ok0 = r0 < R, ok1 = r1 < R;
        const int bi0 = ok0 ? (r0 / rows_per_b) : 0;
        const int bi1 = ok1 ? (r1 / rows_per_b) : 0;
        float p0 = 0.f, p1 = 0.f;
#pragma unroll
        for (int nt = 0; nt < 8; nt++) {
            const int n = n0 + wn + nt * 8 + tig * 2;
            const float v0 = v[n], v1 = v[n + 1];
            p0 = fmaf(v0, tanhf(acc[mt][nt][0] + Cb[(size_t)bi0 * Hd + n]), p0);
            p0 = fmaf(v1, tanhf(acc[mt][nt][1] + Cb[(size_t)bi0 * Hd + n + 1]), p0);
            p1 = fmaf(v0, tanhf(acc[mt][nt][2] + Cb[(size_t)bi1 * Hd + n]), p1);
            p1 = fmaf(v1, tanhf(acc[mt][nt][3] + Cb[(size_t)bi1 * Hd + n + 1]), p1);
        }
        p0 += __shfl_xor_sync(0xffffffffu, p0, 1);
        p0 += __shfl_xor_sync(0xffffffffu, p0, 2);
        p1 += __shfl_xor_sync(0xffffffffu, p1, 1);
        p1 += __shfl_xor_sync(0xffffffffu, p1, 2);
        if (tig == 0) {
            if (ok0) atomicAdd(&outp[r0], p0);
            if (ok1) atomicAdd(&outp[r1], p1);
        }
    }
}

// =================================================================================
// Skinny GEMM v2: warp = 4 columns x 16 rows
// =================================================================================
struct SkJob {
    const float* A;
    const float* W;
    const float* bias;
    float* out;
    int lda, ldw, K, act;
};
struct SkJobs { SkJob j[4]; };

#define SK_CHUNK 128

__global__ __launch_bounds__(256) void skinny_gemm(SkJobs jobs) {
    const SkJob jb = jobs.j[blockIdx.y];
    __shared__ __align__(16) float As[64][SK_CHUNK];
    const int tid = threadIdx.x, warp = tid >> 5, lane = tid & 31;
    const int nb = blockIdx.x * 8 + (warp & 1) * 4;
    const int r0 = (warp >> 1) * 16;

    const float* w0 = jb.W + (size_t)(nb + 0) * jb.ldw;
    const float* w1 = jb.W + (size_t)(nb + 1) * jb.ldw;
    const float* w2 = jb.W + (size_t)(nb + 2) * jb.ldw;
    const float* w3 = jb.W + (size_t)(nb + 3) * jb.ldw;

    float acc[4][16];
#pragma unroll
    for (int c = 0; c < 4; c++)
#pragma unroll
        for (int r = 0; r < 16; r++) acc[c][r] = 0.f;

    for (int kc = 0; kc < jb.K; kc += SK_CHUNK) {
        __syncthreads();
#pragma unroll
        for (int it = 0; it < 8; it++) {
            int idx = tid + it * 256;
            int r = idx >> 5, cc = idx & 31;
            *(float4*)&As[r][cc * 4] =
                *(const float4*)(jb.A + (size_t)r * jb.lda + kc + cc * 4);
        }
        __syncthreads();
        const int ko = kc + lane * 4;
        float4 wv0 = *(const float4*)(w0 + ko);
        float4 wv1 = *(const float4*)(w1 + ko);
        float4 wv2 = *(const float4*)(w2 + ko);
        float4 wv3 = *(const float4*)(w3 + ko);
#pragma unroll
        for (int r = 0; r < 16; r++) {
            float4 a = *(const float4*)&As[r0 + r][lane * 4];
            acc[0][r] = fmaf(wv0.x, a.x, fmaf(wv0.y, a.y, fmaf(wv0.z, a.z, fmaf(wv0.w, a.w, acc[0][r]))));
            acc[1][r] = fmaf(wv1.x, a.x, fmaf(wv1.y, a.y, fmaf(wv1.z, a.z, fmaf(wv1.w, a.w, acc[1][r]))));
            acc[2][r] = fmaf(wv2.x, a.x, fmaf(wv2.y, a.y, fmaf(wv2.z, a.z, fmaf(wv2.w, a.w, acc[2][r]))));
            acc[3][r] = fmaf(wv3.x, a.x, fmaf(wv3.y, a.y, fmaf(wv3.z, a.z, fmaf(wv3.w, a.w, acc[3][r]))));
        }
    }
#pragma unroll
    for (int off = 16; off; off >>= 1)
#pragma unroll
        for (int c = 0; c < 4; c++)
#pragma unroll
            for (int r = 0; r < 16; r++)
                acc[c][r] += __shfl_xor_sync(0xffffffffu, acc[c][r], off);

    float bv0 = jb.bias[nb + 0], bv1 = jb.bias[nb + 1];
    float bv2 = jb.bias[nb + 2], bv3 = jb.bias[nb + 3];
#pragma unroll
    for (int r = 0; r < 16; r++) {
        if (lane == r) {
            float o0 = acc[0][r] + bv0, o1 = acc[1][r] + bv1;
            float o2 = acc[2][r] + bv2, o3 = acc[3][r] + bv3;
            if (jb.act == 1) { o0 = tanhf(o0); o1 = tanhf(o1); o2 = tanhf(o2); o3 = tanhf(o3); }
            float* op = jb.out + (size_t)(r0 + r) * Hd + nb;
            op[0] = o0; op[1] = o1; op[2] = o2; op[3] = o3;
        }
    }
}

// ---------------- small kernels ----------------
__global__ void init_kernel(const float* __restrict__ bs,
                            const float* __restrict__ left_childs,
                            const float* __restrict__ cur_emb)
{
    int i = blockIdx.x * blockDim.x + threadIdx.x;
    if (i < Bd * Sd) { g_energy[i] = bs[0]; return; }
    i -= Bd * Sd;
    if (i < Bd * (NTOT + OPd)) { g_spre[i] = 0.f; return; }
    i -= Bd * (NTOT + OPd);
    if (i < Bd * 2 * Hd) {
        int r = i >> 11, c = i & (2 * Hd - 1);
        g_lc[i] = (c < Hd) ? left_childs[r * Hd + c] : cur_emb[r * Hd + c - Hd];
    }
}

__global__ void node_kernel(const unsigned char* __restrict__ lm, float* o_node) {
    __shared__ int smode;
    if (threadIdx.x == 0) {
        int mode = 0;
        bool nonalign = false;
        for (int t = 1; t < 64; t++)
            if ((t & 3) && lm[t]) { nonalign = true; break; }
        if (nonalign) {
            const unsigned int* w = (const unsigned int*)lm;
            bool isf = true;
            for (int t = 0; t < 16; t++) {
                unsigned int x = w[t];
                if (x != 0u && x != 0x3F800000u) { isf = false; break; }
            }
            mode = isf ? 2 : 1;
        }
        smode = mode;
    }
    __syncthreads();
    int i = blockIdx.x * blockDim.x + threadIdx.x;
    if (i >= Bd * Hd) return;
    int b = i >> 10;
    bool m;
    if (smode == 1)      m = lm[b] != 0;
    else if (smode == 2) m = ((const float*)lm)[b] != 0.f;
    else                 m = ((const int*)lm)[b] != 0;
    float lv = tanhf(g_pre[i]) * (1.f / (1.f + expf(-g_pre[Bd * Hd + i])));
    float rv = tanhf(g_pre[2 * Bd * Hd + i]) * (1.f / (1.f + expf(-g_pre[3 * Bd * Hd + i])));
    float nv = m ? rv : lv;
    g_node[i] = nv;
    o_node[i] = nv;
    g_cat[(size_t)b * 2 * Hd + (i & (Hd - 1))] = nv;
}

__global__ void softmax_kernel(const int* __restrict__ seq_mask) {
    int b = blockIdx.x, s = threadIdx.x;
    __shared__ float red[Sd];
    float val = g_energy[b * Sd + s];
    if (seq_mask[b * Sd + s] == 0) val = NEGV;
    red[s] = val; __syncthreads();
    for (int off = Sd / 2; off > 0; off >>= 1) {
        if (s < off) red[s] = fmaxf(red[s], red[s + off]);
        __syncthreads();
    }
    float mx = red[0]; __syncthreads();
    float ex = expf(val - mx);
    red[s] = ex; __syncthreads();
    for (int off = Sd / 2; off > 0; off >>= 1) {
        if (s < off) red[s] += red[s + off];
        __syncthreads();
    }
    g_energy[b * Sd + s] = ex / red[0];
}

__global__ void ctx_kernel(float* o_ctx) {
    int b = blockIdx.x;
    int h = blockIdx.y * 128 + threadIdx.x;
    __shared__ float aw[Sd];
    for (int i = threadIdx.x; i < Sd; i += 128) aw[i] = g_energy[b * Sd + i];
    __syncthreads();
    const __half* ep = g_ench + (size_t)b * Sd * Hd + h;
    float s0 = 0.f;
#pragma unroll 4
    for (int t = 0; t < Sd; t++)
        s0 = fmaf(aw[t], __half2float(ep[(size_t)t * Hd]), s0);
    o_ctx[b * Hd + h] = s0;
    g_cat[(size_t)b * 2 * Hd + Hd + h] = s0;
}

__global__ void constnum_kernel(const float* __restrict__ cemb,
                                const float* __restrict__ pades, float* o_cn) {
    int i = blockIdx.x * blockDim.x + threadIdx.x;
    if (i >= Bd * NTOT * Hd) return;
    int h = i & (Hd - 1);
    int rn = i >> 10;
    int n = rn % NTOT, b = rn / NTOT;
    o_cn[i] = (n < NCd) ? cemb[n * Hd + h]
                        : pades[((size_t)b * NNd + (n - NCd)) * Hd + h];
}

__global__ void fin_kernel(const int* __restrict__ mask_nums, float* o_num, float* o_op) {
    int i = blockIdx.x * blockDim.x + threadIdx.x;
    if (i < Bd * NTOT) o_num[i] = mask_nums[i] ? g_spre[i] : NEGV;
    if (i < Bd * OPd)  o_op[i]  = g_spre[Bd * NTOT + i];
}

// ---------------- launch ----------------
extern "C" void kernel_launch(void* const* d_in, const int* in_sizes, int n_in,
                              void* d_out, int out_size)
{
    const float* cur_emb     = (const float*)d_in[0];
    const float* left_childs = (const float*)d_in[1];
    const unsigned char* left_mask = (const unsigned char*)d_in[2];
    const float* enc         = (const float*)d_in[3];
    const float* num_pades   = (const float*)d_in[4];
    const int*   seq_mask    = (const int*)d_in[5];
    const int*   mask_nums   = (const int*)d_in[6];
    const float* cemb        = (const float*)d_in[7];
    const float* opemb       = (const float*)d_in[8];
    const float* Wl   = (const float*)d_in[9];
    const float* bl   = (const float*)d_in[10];
    const float* Wlg  = (const float*)d_in[11];
    const float* blg  = (const float*)d_in[12];
    const float* Wr   = (const float*)d_in[13];
    const float* br   = (const float*)d_in[14];
    const float* Wrg  = (const float*)d_in[15];
    const float* brg  = (const float*)d_in[16];
    const float* Wleaf= (const float*)d_in[17];
    const float* bleaf= (const float*)d_in[18];
    const float* Wa   = (const float*)d_in[19];
    const float* ba   = (const float*)d_in[20];
    const float* Ws   = (const float*)d_in[21];
    const float* bs   = (const float*)d_in[22];
    const float* Wna  = (const float*)d_in[23];
    const float* bna  = (const float*)d_in[24];
    const float* Wns  = (const float*)d_in[25];
    const float* Woa  = (const float*)d_in[26];
    const float* boa  = (const float*)d_in[27];
    const float* Wos  = (const float*)d_in[28];

    float* out   = (float*)d_out;
    float* o_num = out;
    float* o_op  = out + 2240;
    float* o_node= out + 2560;
    float* o_ctx = out + 68096;
    float* o_cn  = out + 133632;
    float* o_ope = out + 2427392;

    void* p;
    cudaGetSymbolAddress(&p, g_pre);     float* pre_    = (float*)p;
    cudaGetSymbolAddress(&p, g_lc);      float* lc_     = (float*)p;
    cudaGetSymbolAddress(&p, g_node);    float* node_   = (float*)p;
    cudaGetSymbolAddress(&p, g_cnode);   float* cnode_  = (float*)p;
    cudaGetSymbolAddress(&p, g_energy);  float* energy_ = (float*)p;
    cudaGetSymbolAddress(&p, g_cat);     float* cat_    = (float*)p;
    cudaGetSymbolAddress(&p, g_leaf);    float* leaf_   = (float*)p;
    cudaGetSymbolAddress(&p, g_cnum);    float* cnum_   = (float*)p;
    cudaGetSymbolAddress(&p, g_cop);     float* cop_    = (float*)p;
    cudaGetSymbolAddress(&p, g_spre);    float* spre_   = (float*)p;
    cudaGetSymbolAddress(&p, g_ench);    __half* ench_  = (__half*)p;
    cudaGetSymbolAddress(&p, g_wah);     __half* wah_   = (__half*)p;
    cudaGetSymbolAddress(&p, g_wnah);    __half* wnah_  = (__half*)p;
    cudaGetSymbolAddress(&p, g_woah);    __half* woah_  = (__half*)p;
    cudaGetSymbolAddress(&p, g_aexth);   __half* aexth_ = (__half*)p;

    const int BH = Bd * Hd;

    cudaFuncSetAttribute(mma_energy256, cudaFuncAttributeMaxDynamicSharedMemorySize, ESMEM);
    cudaFuncSetAttribute(mma_f16_score, cudaFuncAttributeMaxDynamicSharedMemorySize, SSMEM);

    // side streams + events (created once; host objects, no device allocation)
    static cudaStream_t s1 = nullptr, s2 = nullptr;
    static cudaEvent_t evFork = nullptr, evCvt = nullptr, evAux = nullptr;
    static cudaEvent_t evPrep = nullptr, evOp = nullptr;
    static cudaEvent_t evLeaf = nullptr, evBias = nullptr;
    if (!s1) {
        cudaStreamCreateWithFlags(&s1, cudaStreamNonBlocking);
        cudaStreamCreateWithFlags(&s2, cudaStreamNonBlocking);
        cudaEventCreateWithFlags(&evFork, cudaEventDisableTiming);
        cudaEventCreateWithFlags(&evCvt, cudaEventDisableTiming);
        cudaEventCreateWithFlags(&evAux, cudaEventDisableTiming);
        cudaEventCreateWithFlags(&evPrep, cudaEventDisableTiming);
        cudaEventCreateWithFlags(&evOp, cudaEventDisableTiming);
        cudaEventCreateWithFlags(&evLeaf, cudaEventDisableTiming);
        cudaEventCreateWithFlags(&evBias, cudaEventDisableTiming);
    }

    // fork
    cudaEventRecord(evFork, 0);
    cudaStreamWaitEvent(s1, evFork, 0);
    cudaStreamWaitEvent(s2, evFork, 0);

    // s1: enc + Wa fp16 convert (gates energies only)
    {
        int tot4 = (32768 * 1024 + 1024 * 1024) / 4;
        cvt_enc_kernel<<<(tot4 + 255) / 256, 256, 0, s1>>>(enc, Wa);
        cudaEventRecord(evCvt, s1);
    }

    // s2: Wna/Woa convert + const_num + emb-half A rows + opemb copy
    {
        int tot4 = (2 * 1024 * 2048) / 4;
        cvt_w_kernel<<<(tot4 + 255) / 256, 256, 0, s2>>>(Wna, Woa);
    }
    constnum_kernel<<<(Bd * NTOT * Hd + 255) / 256, 256, 0, s2>>>(cemb, num_pades, o_cn);
    prep_emb<<<(2560 * 1024 + 255) / 256, 256, 0, s2>>>(o_cn, opemb);
    cudaMemcpyAsync(o_ope, opemb, OPd * Hd * sizeof(float), cudaMemcpyDeviceToDevice, s2);
    cudaEventRecord(evAux, s2);

    // s0: node chain (round-14 proven config)
    {
        int total = Bd * Sd + Bd * (NTOT + OPd) + 2 * BH;
        init_kernel<<<(total + 255) / 256, 256>>>(bs, left_childs, cur_emb);
    }
    {
        SkJobs js;
        js.j[0] = { cur_emb, Wl,  bl,  pre_,           Hd,     Hd,     Hd,     0 };
        js.j[1] = { cur_emb, Wlg, blg, pre_ + BH,      Hd,     Hd,     Hd,     0 };
        js.j[2] = { lc_,     Wr,  br,  pre_ + 2 * BH,  2 * Hd, 2 * Hd, 2 * Hd, 0 };
        js.j[3] = { lc_,     Wrg, brg, pre_ + 3 * BH,  2 * Hd, 2 * Hd, 2 * Hd, 0 };
        skinny_gemm<<<dim3(128, 4), 256>>>(js);
    }
    node_kernel<<<BH / 256, 256>>>(left_mask, o_node);
    {
        SkJobs js;
        js.j[0] = { node_, Wa, ba, cnode_, Hd, 2 * Hd, Hd, 0 };
        skinny_gemm<<<dim3(128, 1), 256>>>(js);
    }

    // join cvt; energies single launch -> softmax -> ctx
    cudaStreamWaitEvent(0, evCvt, 0);
    mma_energy256<<<dim3(8, 256), 256, ESMEM>>>(ench_, wah_, cnode_, Ws, energy_);
    softmax_kernel<<<Bd, Sd>>>(seq_mask);
    dim3 gctx(Bd, 8);
    ctx_kernel<<<gctx, 128>>>(o_ctx);

    // leaf
    {
        SkJobs js;
        js.j[0] = { cat_, Wleaf, bleaf, leaf_, 2 * Hd, 2 * Hd, 2 * Hd, 1 };
        skinny_gemm<<<dim3(128, 1), 256>>>(js);
    }
    cudaEventRecord(evLeaf, 0);

    // s1: per-batch score biases, concurrent with prep_leafemb on s0
    cudaStreamWaitEvent(s1, evLeaf, 0);
    {
        SkJobs js;
        js.j[0] = { leaf_, Wna, bna, cnum_, Hd, 3 * Hd, Hd, 0 };
        js.j[1] = { leaf_, Woa, boa, cop_,  Hd, 3 * Hd, Hd, 0 };
        skinny_gemm<<<dim3(128, 2), 256, 0, s1>>>(js);
    }
    cudaEventRecord(evBias, s1);

    // s0: leaf-half of A rows (needs s2's emb half done)
    cudaStreamWaitEvent(0, evAux, 0);
    prep_leafemb<<<(2560 * 1024 + 255) / 256, 256>>>(o_cn, opemb);
    cudaEventRecord(evPrep, 0);

    // num head on s0 (needs biases), op head concurrently on s1
    cudaStreamWaitEvent(0, evBias, 0);
    mma_f16_score<<<dim3(8, 35), 128, SSMEM>>>(aexth_, wnah_, cnum_, Wns, spre_,
                                               Bd * NTOT, NTOT, 2 * Hd);
    cudaStreamWaitEvent(s1, evPrep, 0);
    mma_f16_score<<<dim3(8, 5), 128, SSMEM, s1>>>(
        aexth_ + (size_t)Bd * NTOT * 2 * Hd, woah_, cop_, Wos, spre_ + Bd * NTOT,
        Bd * OPd, OPd, 2 * Hd);
    cudaEventRecord(evOp, s1);
    cudaStreamWaitEvent(0, evOp, 0);

    fin_kernel<<<(Bd * NTOT + 255) / 256, 256>>>(mask_nums, o_num, o_op);
}